// round 2
// baseline (speedup 1.0000x reference)
#include <cuda_runtime.h>
#include <cstdint>

// CARAFE: features [2,64,64,256] f32, masks [2,128,128,25] f32, k=5, group=1.
// Nearest 64->128 half-pixel => src = dst >> 1; each source pixel feeds a 2x2
// output block sharing its 5x5 patch.
// R2: packed fma.rn.f32x2 (FFMA2) with mask scalars pre-duplicated in smem.

#define FH 64
#define FW 64
#define C4 64      // 256 channels / 4
#define OH 128
#define OW 128
#define KK 25
#define SEGW 8     // source columns per block

// packed f32x2 fma: acc = f * m + acc  (all 64-bit packed pairs)
#define FMA2(acc, f, m) \
    asm("fma.rn.f32x2 %0, %1, %2, %3;" : "=l"(acc) : "l"(f), "l"(m), "l"(acc))

__global__ __launch_bounds__(64)
void carafe_kernel(const float* __restrict__ features,
                   const float* __restrict__ masks,
                   float* __restrict__ out)
{
    // smaskD layout: [px(8)][tap(25)][8 floats] = {mx,mx, my,my, mz,mz, mw,mw}
    // readable as two ulonglong2 (LDS.128) per tap, each half a duplicated scalar.
    __shared__ __align__(16) float smaskD[SEGW * KK * 8];

    const int tid = threadIdx.x;
    const int seg = blockIdx.x;
    const int hs  = blockIdx.y;
    const int b   = blockIdx.z;
    const int ws0 = seg * SEGW;

    // ---- cooperative mask load + duplicate: 800 source floats -> 1600 smem ----
    {
        const int mrow0 = ((b * OH + 2 * hs    ) * OW + 2 * ws0) * KK;
        const int mrow1 = ((b * OH + 2 * hs + 1) * OW + 2 * ws0) * KK;
        #pragma unroll
        for (int it = 0; it < 13; it++) {
            int idx = tid + it * 64;
            if (idx < 800) {
                int oy   = idx / 400;          // 0..1
                int j    = idx - oy * 400;     // contiguous within global mask row
                int wrel = j / KK;             // 0..15 output col within segment
                int p    = j - wrel * KK;      // tap
                int px   = wrel >> 1;          // source col in segment
                int ox   = wrel & 1;
                float v = masks[(oy ? mrow1 : mrow0) + j];
                int base = px * (KK * 8) + p * 8 + (oy * 2 + ox) * 2;
                smaskD[base]     = v;
                smaskD[base + 1] = v;
            }
        }
    }
    __syncthreads();

    const ulonglong2* __restrict__ F = (const ulonglong2*)features;
    const int c4 = tid;

    bool rowok[5];
    int  rowbase[5];
    #pragma unroll
    for (int r = 0; r < 5; r++) {
        int hr = hs - 2 + r;
        rowok[r]   = (hr >= 0) && (hr < FH);
        rowbase[r] = ((b * FH + hr) * FW) * C4 + c4;
    }

    const ulonglong2 Z2 = make_ulonglong2(0ull, 0ull);

    // rolling 5x5 window of packed-f32x2 pairs (.x = ch01, .y = ch23)
    ulonglong2 win[5][5];
    #pragma unroll
    for (int cc = 0; cc < 5; cc++) {
        int wc = ws0 - 2 + cc;
        bool colok = (wc >= 0) && (wc < FW);
        #pragma unroll
        for (int r = 0; r < 5; r++)
            win[r][cc] = (rowok[r] && colok) ? F[rowbase[r] + wc * C4] : Z2;
    }

    ulonglong2* __restrict__ O = (ulonglong2*)out;

    #pragma unroll
    for (int s = 0; s < SEGW; s++) {
        const int ws = ws0 + s;
        const ulonglong2* __restrict__ mp =
            (const ulonglong2*)&smaskD[s * (KK * 8)];

        unsigned long long a0l = 0, a0h = 0, a1l = 0, a1h = 0;
        unsigned long long a2l = 0, a2h = 0, a3l = 0, a3h = 0;

        #pragma unroll
        for (int p = 0; p < KK; p++) {
            const ulonglong2 f  = win[p / 5][p % 5];
            const ulonglong2 mA = mp[2 * p];       // {mx2, my2}
            const ulonglong2 mB = mp[2 * p + 1];   // {mz2, mw2}
            FMA2(a0l, f.x, mA.x); FMA2(a0h, f.y, mA.x);   // (oy0,ox0)
            FMA2(a1l, f.x, mA.y); FMA2(a1h, f.y, mA.y);   // (oy0,ox1)
            FMA2(a2l, f.x, mB.x); FMA2(a2h, f.y, mB.x);   // (oy1,ox0)
            FMA2(a3l, f.x, mB.y); FMA2(a3h, f.y, mB.y);   // (oy1,ox1)
        }

        const int ob0 = ((b * OH + 2 * hs    ) * OW + 2 * ws) * C4 + c4;
        const int ob1 = ((b * OH + 2 * hs + 1) * OW + 2 * ws) * C4 + c4;
        O[ob0]      = make_ulonglong2(a0l, a0h);
        O[ob0 + C4] = make_ulonglong2(a1l, a1h);
        O[ob1]      = make_ulonglong2(a2l, a2h);
        O[ob1 + C4] = make_ulonglong2(a3l, a3h);

        if (s < SEGW - 1) {
            #pragma unroll
            for (int r = 0; r < 5; r++) {
                win[r][0] = win[r][1];
                win[r][1] = win[r][2];
                win[r][2] = win[r][3];
                win[r][3] = win[r][4];
            }
            const int wc = ws + 3;           // always >= 3 here
            const bool colok = (wc < FW);
            #pragma unroll
            for (int r = 0; r < 5; r++)
                win[r][4] = (rowok[r] && colok) ? F[rowbase[r] + wc * C4] : Z2;
        }
    }
}

extern "C" void kernel_launch(void* const* d_in, const int* in_sizes, int n_in,
                              void* d_out, int out_size) {
    const float* features = (const float*)d_in[0];
    const float* masks    = (const float*)d_in[1];
    float* out            = (float*)d_out;

    dim3 grid(FW / SEGW, FH, 2);   // (8, 64, 2) = 1024 blocks
    carafe_kernel<<<grid, 64>>>(features, masks, out);
}

// round 3
// speedup vs baseline: 1.2172x; 1.2172x over previous
#include <cuda_runtime.h>

// CARAFE: features [2,64,64,256] f32, masks [2,128,128,25] f32, k=5, group=1.
// Nearest 64->128 half-pixel => src = dst >> 1; each source pixel feeds a 2x2
// output block sharing its 5x5 patch.
// R3: scalar FFMA (R1 structure) but float2 channel groups + 128 threads/block
//     to double resident warps/SM (occupancy was the R1/R2 limiter).

#define FH 64
#define FW 64
#define C2 128     // 256 channels / 2
#define OH 128
#define OW 128
#define KK 25
#define SEGW 8     // source columns per block

__device__ __forceinline__ void fma2s(float2& a, const float2 f, const float m) {
    a.x = fmaf(f.x, m, a.x);
    a.y = fmaf(f.y, m, a.y);
}

__global__ __launch_bounds__(128, 6)
void carafe_kernel(const float* __restrict__ features,
                   const float* __restrict__ masks,
                   float* __restrict__ out)
{
    // smask layout: [px(8)][tap(25)][out(4)] (out = oy*2+ox), float4-readable per tap
    __shared__ __align__(16) float smask[SEGW * KK * 4];

    const int tid = threadIdx.x;
    const int seg = blockIdx.x;
    const int hs  = blockIdx.y;
    const int b   = blockIdx.z;
    const int ws0 = seg * SEGW;

    // ---- cooperative mask load: 2 output rows x 16 output cols x 25 taps = 800 floats ----
    {
        const int mrow0 = ((b * OH + 2 * hs    ) * OW + 2 * ws0) * KK;
        const int mrow1 = ((b * OH + 2 * hs + 1) * OW + 2 * ws0) * KK;
        #pragma unroll
        for (int it = 0; it < 7; it++) {
            int idx = tid + it * 128;
            if (idx < 800) {
                int oy   = idx / 400;          // 0..1
                int j    = idx - oy * 400;     // contiguous within the global mask row
                int wrel = j / KK;             // 0..15 output col within segment
                int p    = j - wrel * KK;      // tap
                int px   = wrel >> 1;          // source col within segment
                int ox   = wrel & 1;
                float v = masks[(oy ? mrow1 : mrow0) + j];
                smask[px * (KK * 4) + p * 4 + oy * 2 + ox] = v;
            }
        }
    }
    __syncthreads();

    const float2* __restrict__ F = (const float2*)features;
    const int c2 = tid;  // this thread's float2 channel group (0..127)

    bool rowok[5];
    int  rowbase[5];
    #pragma unroll
    for (int r = 0; r < 5; r++) {
        int hr = hs - 2 + r;
        rowok[r]   = (hr >= 0) && (hr < FH);
        rowbase[r] = ((b * FH + hr) * FW) * C2 + c2;
    }

    // ---- rolling 5x5 float2 register window (50 regs); unrolled shifts = renames ----
    float2 win[5][5];
    #pragma unroll
    for (int cc = 0; cc < 5; cc++) {
        int wc = ws0 - 2 + cc;
        bool colok = (wc >= 0) && (wc < FW);
        #pragma unroll
        for (int r = 0; r < 5; r++) {
            win[r][cc] = (rowok[r] && colok) ? F[rowbase[r] + wc * C2]
                                             : make_float2(0.f, 0.f);
        }
    }

    float2* __restrict__ O = (float2*)out;

    #pragma unroll
    for (int s = 0; s < SEGW; s++) {
        const int ws = ws0 + s;
        const float4* __restrict__ mp = (const float4*)&smask[s * (KK * 4)];

        float2 a0 = make_float2(0.f, 0.f);
        float2 a1 = a0, a2 = a0, a3 = a0;

        #pragma unroll
        for (int p = 0; p < KK; p++) {
            const float2 f = win[p / 5][p % 5];
            const float4 m = mp[p];            // broadcast LDS.128: 4 outputs' masks at tap p
            fma2s(a0, f, m.x);                 // (oy=0, ox=0)
            fma2s(a1, f, m.y);                 // (oy=0, ox=1)
            fma2s(a2, f, m.z);                 // (oy=1, ox=0)
            fma2s(a3, f, m.w);                 // (oy=1, ox=1)
        }

        const int ob0 = ((b * OH + 2 * hs    ) * OW + 2 * ws) * C2 + c2;
        const int ob1 = ((b * OH + 2 * hs + 1) * OW + 2 * ws) * C2 + c2;
        O[ob0]      = a0;
        O[ob0 + C2] = a1;
        O[ob1]      = a2;
        O[ob1 + C2] = a3;

        if (s < SEGW - 1) {
            #pragma unroll
            for (int r = 0; r < 5; r++) {
                win[r][0] = win[r][1];
                win[r][1] = win[r][2];
                win[r][2] = win[r][3];
                win[r][3] = win[r][4];
            }
            const int wc = ws + 3;          // always >= 3 here
            const bool colok = (wc < FW);
            #pragma unroll
            for (int r = 0; r < 5; r++) {
                win[r][4] = (rowok[r] && colok) ? F[rowbase[r] + wc * C2]
                                                : make_float2(0.f, 0.f);
            }
        }
    }
}

extern "C" void kernel_launch(void* const* d_in, const int* in_sizes, int n_in,
                              void* d_out, int out_size) {
    const float* features = (const float*)d_in[0];
    const float* masks    = (const float*)d_in[1];
    float* out            = (float*)d_out;

    dim3 grid(FW / SEGW, FH, 2);   // (8, 64, 2) = 1024 blocks x 4 warps
    carafe_kernel<<<grid, 128>>>(features, masks, out);
}

// round 4
// speedup vs baseline: 1.3397x; 1.1006x over previous
#include <cuda_runtime.h>

// CARAFE: features [2,64,64,256] f32, masks [2,128,128,25] f32, k=5, group=1.
// Nearest 64->128 half-pixel => src = dst >> 1; each source pixel feeds a 2x2
// output block sharing its 5x5 patch.
// R4: instruction diet. Rotating window slots (no shift MOVs), immediate-offset
//     LDG/STG addressing, interior/border template split (no bounds SELs for
//     70% of blocks).

#define FH 64
#define FW 64
#define C2 128     // 256 channels / 2 (float2 groups)
#define OH 128
#define OW 128
#define KK 25
#define SEGW 8

__device__ __forceinline__ void fma2s(float2& a, const float2 f, const float m) {
    a.x = fmaf(f.x, m, a.x);
    a.y = fmaf(f.y, m, a.y);
}

template<bool CHK>
__device__ __forceinline__ void carafe_body(int seg, int hs, int b,
                                            const float2* __restrict__ F,
                                            float2* __restrict__ O,
                                            const float* __restrict__ smask,
                                            int c2)
{
    const int ws0 = seg * SEGW;
    const float2 z = make_float2(0.f, 0.f);

    // per-row base pointers at column (ws0 - 2); all later column accesses are
    // compile-time immediate offsets (j * C2 float2 = j * 1024 bytes).
    const float2* q[5];
    bool rok[5];
    #pragma unroll
    for (int r = 0; r < 5; r++) {
        int hr = hs - 2 + r;
        rok[r] = CHK ? (hr >= 0 && hr < FH) : true;
        q[r] = F + ((long)(b * FH + hr) * FW + (ws0 - 2)) * C2 + c2;
    }

    // initial 5x5 window: col (ws0-2+j) lives in slot j = (col - ws0 + 2) % 5
    float2 w[5][5];
    #pragma unroll
    for (int j = 0; j < 5; j++) {
        bool cok = CHK ? ((ws0 - 2 + j) >= 0 && (ws0 - 2 + j) < FW) : true;
        #pragma unroll
        for (int r = 0; r < 5; r++)
            w[r][j] = (rok[r] && cok) ? q[r][j * C2] : z;
    }

    // output base pointers (row 2*hs / 2*hs+1, col 2*ws0); per-pixel stores use
    // compile-time immediate offsets.
    float2* o0 = O + ((long)(b * OH + 2 * hs) * OW + 2 * ws0) * C2 + c2;
    float2* o1 = o0 + (long)OW * C2;

    #pragma unroll
    for (int s = 0; s < SEGW; s++) {
        const float4* __restrict__ mp = (const float4*)(smask + s * (KK * 4));

        float2 a0 = z, a1 = z, a2 = z, a3 = z;

        #pragma unroll
        for (int p = 0; p < KK; p++) {
            const int r = p / 5;
            const int d = p % 5;
            const float2 f = w[r][(s + d) % 5];   // compile-time slot
            const float4 m = mp[p];               // LDS.128 broadcast: 4 outputs' masks
            fma2s(a0, f, m.x);
            fma2s(a1, f, m.y);
            fma2s(a2, f, m.z);
            fma2s(a3, f, m.w);
        }

        o0[(2 * s) * C2]     = a0;
        o0[(2 * s + 1) * C2] = a1;
        o1[(2 * s) * C2]     = a2;
        o1[(2 * s + 1) * C2] = a3;

        if (s < SEGW - 1) {
            // refill col (ws0 + s + 3) into slot (s % 5); offset (s+5)*C2 is immediate
            const bool cok = CHK ? ((ws0 + s + 3) < FW) : true;
            #pragma unroll
            for (int r = 0; r < 5; r++)
                w[r][s % 5] = (rok[r] && cok) ? q[r][(s + 5) * C2] : z;
        }
    }
}

__global__ __launch_bounds__(128)
void carafe_kernel(const float* __restrict__ features,
                   const float* __restrict__ masks,
                   float* __restrict__ out)
{
    // smask layout: [px(8)][tap(25)][out(4)], out = oy*2+ox; float4-readable per tap
    __shared__ __align__(16) float smask[SEGW * KK * 4];

    const int tid = threadIdx.x;
    const int seg = blockIdx.x;
    const int hs  = blockIdx.y;
    const int b   = blockIdx.z;
    const int ws0 = seg * SEGW;

    // cooperative mask stage: 2 output rows x 16 output cols x 25 taps = 800 floats
    {
        const int mrow0 = ((b * OH + 2 * hs    ) * OW + 2 * ws0) * KK;
        const int mrow1 = ((b * OH + 2 * hs + 1) * OW + 2 * ws0) * KK;
        #pragma unroll
        for (int it = 0; it < 7; it++) {
            int idx = tid + it * 128;
            if (idx < 800) {
                int oy   = idx / 400;
                int j    = idx - oy * 400;
                int wrel = j / KK;
                int p    = j - wrel * KK;
                int px   = wrel >> 1;
                int ox   = wrel & 1;
                float v = masks[(oy ? mrow1 : mrow0) + j];
                smask[px * (KK * 4) + p * 4 + oy * 2 + ox] = v;
            }
        }
    }
    __syncthreads();

    const float2* F = (const float2*)features;
    float2* O = (float2*)out;

    const bool interior = (seg >= 1) && (seg <= 6) && (hs >= 2) && (hs <= 61);
    if (interior)
        carafe_body<false>(seg, hs, b, F, O, smask, tid);
    else
        carafe_body<true>(seg, hs, b, F, O, smask, tid);
}

extern "C" void kernel_launch(void* const* d_in, const int* in_sizes, int n_in,
                              void* d_out, int out_size) {
    const float* features = (const float*)d_in[0];
    const float* masks    = (const float*)d_in[1];
    float* out            = (float*)d_out;

    dim3 grid(FW / SEGW, FH, 2);   // (8, 64, 2) = 1024 blocks x 4 warps
    carafe_kernel<<<grid, 128>>>(features, masks, out);
}